// round 4
// baseline (speedup 1.0000x reference)
#include <cuda_runtime.h>
#include <cstdint>
#include <cstddef>

#define BATCH 4
#define SEQT  2048
#define CIN   1152
#define NE    1024
#define NH    16
#define HD    64
#define ROWS  (BATCH*SEQT)   // 8192

// ---- scratch (no allocations allowed) ----
__device__ float g_h[(size_t)ROWS * CIN];        // LN output, tf32-rounded
__device__ float g_qkv[(size_t)ROWS * 3 * NE];   // QKV, fp32
__device__ float g_y[(size_t)ROWS * NE];         // attention out, tf32-rounded

__device__ __forceinline__ uint32_t f2tf(float x) {
    uint32_t r; asm("cvt.rna.tf32.f32 %0, %1;" : "=r"(r) : "f"(x)); return r;
}
__device__ __forceinline__ float f2tff(float x) { return __uint_as_float(f2tf(x)); }

__device__ __forceinline__ void mma_tf32(float c[4], const uint32_t a[4], const uint32_t b[2]) {
    asm volatile(
        "mma.sync.aligned.m16n8k8.row.col.f32.tf32.tf32.f32 "
        "{%0,%1,%2,%3}, {%4,%5,%6,%7}, {%8,%9}, {%0,%1,%2,%3};\n"
        : "+f"(c[0]), "+f"(c[1]), "+f"(c[2]), "+f"(c[3])
        : "r"(a[0]), "r"(a[1]), "r"(a[2]), "r"(a[3]), "r"(b[0]), "r"(b[1]));
}

// ------------------------- LayerNorm -------------------------
__global__ void ln_kernel(const float* __restrict__ x, const float* __restrict__ w,
                          const float* __restrict__ bb, float* __restrict__ h) {
    int row = blockIdx.x;
    const float* xr = x + (size_t)row * CIN;
    float s1 = 0.f, s2 = 0.f;
    for (int i = threadIdx.x; i < CIN; i += 256) { float v = xr[i]; s1 += v; s2 += v * v; }
    #pragma unroll
    for (int o = 16; o; o >>= 1) {
        s1 += __shfl_xor_sync(0xffffffffu, s1, o);
        s2 += __shfl_xor_sync(0xffffffffu, s2, o);
    }
    __shared__ float sh1[8], sh2[8];
    int wid = threadIdx.x >> 5, lane = threadIdx.x & 31;
    if (lane == 0) { sh1[wid] = s1; sh2[wid] = s2; }
    __syncthreads();
    float S1 = 0.f, S2 = 0.f;
    #pragma unroll
    for (int i = 0; i < 8; i++) { S1 += sh1[i]; S2 += sh2[i]; }
    float mean = S1 * (1.f / CIN);
    float var  = S2 * (1.f / CIN) - mean * mean;
    float inv  = rsqrtf(var + 1e-5f);
    float* hr = h + (size_t)row * CIN;
    for (int i = threadIdx.x; i < CIN; i += 256)
        hr[i] = f2tff((xr[i] - mean) * inv * w[i] + bb[i]);
}

// ------------------------- TF32 GEMM: C = A@B + bias -------------------------
__global__ __launch_bounds__(256) void gemm_tf32(
        const float* __restrict__ A, const float* __restrict__ Bm,
        const float* __restrict__ bias, float* __restrict__ C,
        int M, int N, int K) {
    __shared__ float As[128][20];
    __shared__ float Bs[16][136];
    int tid = threadIdx.x;
    int lane = tid & 31, wid = tid >> 5;
    int wm = (wid & 3) * 32, wn = (wid >> 2) * 64;
    int bm = blockIdx.y * 128, bn = blockIdx.x * 128;
    int g = lane >> 2, tg = lane & 3;

    float acc[2][8][4];
    #pragma unroll
    for (int mt = 0; mt < 2; mt++)
        #pragma unroll
        for (int nt = 0; nt < 8; nt++)
            #pragma unroll
            for (int i = 0; i < 4; i++) acc[mt][nt][i] = 0.f;

    for (int k0 = 0; k0 < K; k0 += 16) {
        #pragma unroll
        for (int i = 0; i < 2; i++) {
            int f = tid + i * 256;
            int r = f >> 2, c = (f & 3) * 4;
            float4 v = *reinterpret_cast<const float4*>(A + (size_t)(bm + r) * K + k0 + c);
            As[r][c + 0] = v.x; As[r][c + 1] = v.y; As[r][c + 2] = v.z; As[r][c + 3] = v.w;
        }
        #pragma unroll
        for (int i = 0; i < 2; i++) {
            int f = tid + i * 256;
            int r = f >> 5, c = (f & 31) * 4;
            float4 v = *reinterpret_cast<const float4*>(Bm + (size_t)(k0 + r) * N + bn + c);
            Bs[r][c + 0] = f2tff(v.x); Bs[r][c + 1] = f2tff(v.y);
            Bs[r][c + 2] = f2tff(v.z); Bs[r][c + 3] = f2tff(v.w);
        }
        __syncthreads();
        #pragma unroll
        for (int ks = 0; ks < 2; ks++) {
            uint32_t a[2][4], b[8][2];
            #pragma unroll
            for (int mt = 0; mt < 2; mt++) {
                int r = wm + mt * 16 + g, c = ks * 8 + tg;
                a[mt][0] = __float_as_uint(As[r][c]);
                a[mt][1] = __float_as_uint(As[r + 8][c]);
                a[mt][2] = __float_as_uint(As[r][c + 4]);
                a[mt][3] = __float_as_uint(As[r + 8][c + 4]);
            }
            #pragma unroll
            for (int nt = 0; nt < 8; nt++) {
                int c = wn + nt * 8 + g, r = ks * 8 + tg;
                b[nt][0] = __float_as_uint(Bs[r][c]);
                b[nt][1] = __float_as_uint(Bs[r + 4][c]);
            }
            #pragma unroll
            for (int mt = 0; mt < 2; mt++)
                #pragma unroll
                for (int nt = 0; nt < 8; nt++)
                    mma_tf32(acc[mt][nt], a[mt], b[nt]);
        }
        __syncthreads();
    }
    #pragma unroll
    for (int mt = 0; mt < 2; mt++) {
        int r0 = bm + wm + mt * 16 + g;
        #pragma unroll
        for (int nt = 0; nt < 8; nt++) {
            int c0 = bn + wn + nt * 8 + tg * 2;
            float bz0 = bias[c0], bz1 = bias[c0 + 1];
            C[(size_t)r0 * N + c0]       = acc[mt][nt][0] + bz0;
            C[(size_t)r0 * N + c0 + 1]   = acc[mt][nt][1] + bz1;
            C[(size_t)(r0 + 8) * N + c0]     = acc[mt][nt][2] + bz0;
            C[(size_t)(r0 + 8) * N + c0 + 1] = acc[mt][nt][3] + bz1;
        }
    }
}

// ------------------------- Flash attention (causal) -------------------------
// Block = (q-tile 128 rows, head, batch). 8 warps x 16 q-rows each.
// TF32 mma for S = Q K^T and O += P V. P converted acc->A-frag via shuffles
// (no smem round-trip). K tile 64 rows.
__global__ __launch_bounds__(256, 2) void attn_kernel(const float* __restrict__ qkv,
                                                      float* __restrict__ y) {
    __shared__ float bufK[64][68];
    __shared__ float bufV[64][68];
    int qt = blockIdx.x, h = blockIdx.y, b = blockIdx.z;
    int tid = threadIdx.x, lane = tid & 31, w = tid >> 5;
    int g = lane >> 2, tg = lane & 3;
    int q0 = qt * 128;
    int row0 = q0 + w * 16;           // first q-row of this warp
    const size_t rstr = (size_t)3 * NE;
    const float* kbase = qkv + ((size_t)b * SEQT) * rstr + NE + h * HD;
    const float* vbase = qkv + ((size_t)b * SEQT) * rstr + 2 * NE + h * HD;

    // Q fragments: direct gmem loads (once per block, amortized over ~17 tiles)
    const float scale = 0.125f;
    const float* qbase = qkv + ((size_t)b * SEQT + row0) * rstr + h * HD;
    uint32_t qf[8][4];
    #pragma unroll
    for (int ks = 0; ks < 8; ks++) {
        int c = ks * 8 + tg;
        qf[ks][0] = f2tf(qbase[(size_t)g * rstr + c] * scale);
        qf[ks][1] = f2tf(qbase[(size_t)(g + 8) * rstr + c] * scale);
        qf[ks][2] = f2tf(qbase[(size_t)g * rstr + c + 4] * scale);
        qf[ks][3] = f2tf(qbase[(size_t)(g + 8) * rstr + c + 4] * scale);
    }

    float O[8][4];
    #pragma unroll
    for (int dt = 0; dt < 8; dt++)
        #pragma unroll
        for (int i = 0; i < 4; i++) O[dt][i] = 0.f;
    float m0 = -1e30f, m1 = -1e30f, l0 = 0.f, l1 = 0.f;

    int src0 = (lane & ~3) + (tg >> 1);   // P-shuffle source lanes
    int src1 = src0 + 2;
    int e = tg & 1;

    int ktmax = 2 * qt + 1;               // tiles covering cols < q0+128
    for (int kt = 0; kt <= ktmax; kt++) {
        int kb = kt * 64;
        // cooperative K/V tile load, tf32-rounded at store
        #pragma unroll
        for (int i = 0; i < 4; i++) {
            int idx = tid + i * 256;      // 0..1023
            int r = idx >> 4, c = (idx & 15) * 4;
            float4 kv4 = *reinterpret_cast<const float4*>(kbase + (size_t)(kb + r) * rstr + c);
            bufK[r][c + 0] = f2tff(kv4.x); bufK[r][c + 1] = f2tff(kv4.y);
            bufK[r][c + 2] = f2tff(kv4.z); bufK[r][c + 3] = f2tff(kv4.w);
            float4 vv4 = *reinterpret_cast<const float4*>(vbase + (size_t)(kb + r) * rstr + c);
            bufV[r][c + 0] = f2tff(vv4.x); bufV[r][c + 1] = f2tff(vv4.y);
            bufV[r][c + 2] = f2tff(vv4.z); bufV[r][c + 3] = f2tff(vv4.w);
        }
        __syncthreads();

        if (kb <= row0 + 15) {            // tile not fully masked for this warp
            float S[8][4];
            #pragma unroll
            for (int nt = 0; nt < 8; nt++)
                #pragma unroll
                for (int i = 0; i < 4; i++) S[nt][i] = 0.f;
            #pragma unroll
            for (int ks = 0; ks < 8; ks++) {
                uint32_t bk[8][2];
                #pragma unroll
                for (int nt = 0; nt < 8; nt++) {
                    bk[nt][0] = __float_as_uint(bufK[nt * 8 + g][ks * 8 + tg]);
                    bk[nt][1] = __float_as_uint(bufK[nt * 8 + g][ks * 8 + tg + 4]);
                }
                #pragma unroll
                for (int nt = 0; nt < 8; nt++) mma_tf32(S[nt], qf[ks], bk[nt]);
            }

            if (kb + 63 > row0) {         // straddles the diagonal: elementwise mask
                int r = row0 + g;
                #pragma unroll
                for (int nt = 0; nt < 8; nt++) {
                    int c = kb + nt * 8 + tg * 2;
                    if (c     > r)     S[nt][0] = -1e30f;
                    if (c + 1 > r)     S[nt][1] = -1e30f;
                    if (c     > r + 8) S[nt][2] = -1e30f;
                    if (c + 1 > r + 8) S[nt][3] = -1e30f;
                }
            }

            float mx0 = -1e30f, mx1 = -1e30f;
            #pragma unroll
            for (int nt = 0; nt < 8; nt++) {
                mx0 = fmaxf(mx0, fmaxf(S[nt][0], S[nt][1]));
                mx1 = fmaxf(mx1, fmaxf(S[nt][2], S[nt][3]));
            }
            #pragma unroll
            for (int o = 1; o <= 2; o <<= 1) {
                mx0 = fmaxf(mx0, __shfl_xor_sync(0xffffffffu, mx0, o));
                mx1 = fmaxf(mx1, __shfl_xor_sync(0xffffffffu, mx1, o));
            }
            float nm0 = fmaxf(m0, mx0), nm1 = fmaxf(m1, mx1);
            float al0 = __expf(m0 - nm0), al1 = __expf(m1 - nm1);
            float rs0 = 0.f, rs1 = 0.f;
            #pragma unroll
            for (int nt = 0; nt < 8; nt++) {
                S[nt][0] = __expf(S[nt][0] - nm0); rs0 += S[nt][0];
                S[nt][1] = __expf(S[nt][1] - nm0); rs0 += S[nt][1];
                S[nt][2] = __expf(S[nt][2] - nm1); rs1 += S[nt][2];
                S[nt][3] = __expf(S[nt][3] - nm1); rs1 += S[nt][3];
            }
            #pragma unroll
            for (int o = 1; o <= 2; o <<= 1) {
                rs0 += __shfl_xor_sync(0xffffffffu, rs0, o);
                rs1 += __shfl_xor_sync(0xffffffffu, rs1, o);
            }
            l0 = l0 * al0 + rs0; l1 = l1 * al1 + rs1;
            m0 = nm0; m1 = nm1;
            #pragma unroll
            for (int dt = 0; dt < 8; dt++) {
                O[dt][0] *= al0; O[dt][1] *= al0; O[dt][2] *= al1; O[dt][3] *= al1;
            }

            // round P to tf32 in-register
            #pragma unroll
            for (int nt = 0; nt < 8; nt++)
                #pragma unroll
                for (int i = 0; i < 4; i++) S[nt][i] = f2tff(S[nt][i]);

            // P·V: convert accumulator layout -> A-fragment layout via shuffles
            #pragma unroll
            for (int ks = 0; ks < 8; ks++) {
                float v0 = __shfl_sync(0xffffffffu, S[ks][0], src0);
                float v1 = __shfl_sync(0xffffffffu, S[ks][1], src0);
                float v2 = __shfl_sync(0xffffffffu, S[ks][2], src0);
                float v3 = __shfl_sync(0xffffffffu, S[ks][3], src0);
                float u0 = __shfl_sync(0xffffffffu, S[ks][0], src1);
                float u1 = __shfl_sync(0xffffffffu, S[ks][1], src1);
                float u2 = __shfl_sync(0xffffffffu, S[ks][2], src1);
                float u3 = __shfl_sync(0xffffffffu, S[ks][3], src1);
                uint32_t pa[4];
                pa[0] = __float_as_uint(e ? v1 : v0);
                pa[1] = __float_as_uint(e ? v3 : v2);
                pa[2] = __float_as_uint(e ? u1 : u0);
                pa[3] = __float_as_uint(e ? u3 : u2);
                #pragma unroll
                for (int dt = 0; dt < 8; dt++) {
                    uint32_t bv[2];
                    bv[0] = __float_as_uint(bufV[ks * 8 + tg][dt * 8 + g]);
                    bv[1] = __float_as_uint(bufV[ks * 8 + tg + 4][dt * 8 + g]);
                    mma_tf32(O[dt], pa, bv);
                }
            }
        }
        __syncthreads();   // before next tile overwrites K/V
    }

    float il0 = 1.f / l0, il1 = 1.f / l1;
    int r = row0 + g;
    float* yb  = y + ((size_t)b * SEQT + r) * NE + h * HD;
    float* yb8 = y + ((size_t)b * SEQT + r + 8) * NE + h * HD;
    #pragma unroll
    for (int dt = 0; dt < 8; dt++) {
        int c = dt * 8 + tg * 2;
        yb[c]      = f2tff(O[dt][0] * il0);
        yb[c + 1]  = f2tff(O[dt][1] * il0);
        yb8[c]     = f2tff(O[dt][2] * il1);
        yb8[c + 1] = f2tff(O[dt][3] * il1);
    }
}

// ------------------------- launch -------------------------
extern "C" void kernel_launch(void* const* d_in, const int* in_sizes, int n_in,
                              void* d_out, int out_size) {
    const float* x      = (const float*)d_in[0];
    const float* ln_w   = (const float*)d_in[1];
    const float* ln_b   = (const float*)d_in[2];
    const float* W_attn = (const float*)d_in[3];
    const float* b_attn = (const float*)d_in[4];
    const float* W_proj = (const float*)d_in[5];
    const float* b_proj = (const float*)d_in[6];
    float* out = (float*)d_out;

    float *h, *qkv, *y;
    cudaGetSymbolAddress((void**)&h,   g_h);
    cudaGetSymbolAddress((void**)&qkv, g_qkv);
    cudaGetSymbolAddress((void**)&y,   g_y);

    ln_kernel<<<ROWS, 256>>>(x, ln_w, ln_b, h);
    gemm_tf32<<<dim3(3 * NE / 128, ROWS / 128), 256>>>(h, W_attn, b_attn, qkv, ROWS, 3 * NE, CIN);
    attn_kernel<<<dim3(SEQT / 128, NH, BATCH), 256>>>(qkv, y);
    gemm_tf32<<<dim3(NE / 128, ROWS / 128), 256>>>(y, W_proj, b_proj, out, ROWS, NE, NE);
}

// round 8
// speedup vs baseline: 1.7792x; 1.7792x over previous
#include <cuda_runtime.h>
#include <cuda_fp16.h>
#include <cstdint>
#include <cstddef>

#define BATCH 4
#define SEQT  2048
#define CIN   1152
#define NE    1024
#define NH    16
#define HD    64
#define ROWS  (BATCH*SEQT)   // 8192

// ---- scratch (no allocations allowed) ----
__device__ __half g_h[(size_t)ROWS * CIN];          // LN output (half)
__device__ __half g_qkv[(size_t)ROWS * 3 * NE];     // QKV (half)
__device__ __half g_y[(size_t)ROWS * NE];           // attention out (half)
__device__ __half g_wta[(size_t)3 * NE * CIN];      // W_attn^T [N,K] half
__device__ __half g_wtp[(size_t)NE * NE];           // W_proj^T [N,K] half

__device__ __forceinline__ void mma_f16(float c[4], const uint32_t a[4], const uint32_t b[2]) {
    asm volatile(
        "mma.sync.aligned.m16n8k16.row.col.f32.f16.f16.f32 "
        "{%0,%1,%2,%3}, {%4,%5,%6,%7}, {%8,%9}, {%0,%1,%2,%3};\n"
        : "+f"(c[0]), "+f"(c[1]), "+f"(c[2]), "+f"(c[3])
        : "r"(a[0]), "r"(a[1]), "r"(a[2]), "r"(a[3]), "r"(b[0]), "r"(b[1]));
}

// ---------------- weight transpose + half convert: wT[n][k] = (half)W[k][n] ----------------
__global__ void transpose_w(const float* __restrict__ W, __half* __restrict__ wT, int K, int N) {
    __shared__ float t[32][33];
    int n0 = blockIdx.x * 32, k0 = blockIdx.y * 32;
    #pragma unroll
    for (int i = threadIdx.y; i < 32; i += 8)
        t[i][threadIdx.x] = W[(size_t)(k0 + i) * N + n0 + threadIdx.x];
    __syncthreads();
    #pragma unroll
    for (int i = threadIdx.y; i < 32; i += 8)
        wT[(size_t)(n0 + i) * K + k0 + threadIdx.x] = __float2half_rn(t[threadIdx.x][i]);
}

// ------------------------- LayerNorm (writes half) -------------------------
__global__ void ln_kernel(const float* __restrict__ x, const float* __restrict__ w,
                          const float* __restrict__ bb, __half* __restrict__ h) {
    int row = blockIdx.x;
    const float2* xr = (const float2*)(x + (size_t)row * CIN);   // 576 float2
    float s1 = 0.f, s2 = 0.f;
    for (int i = threadIdx.x; i < CIN / 2; i += 256) {
        float2 v = xr[i];
        s1 += v.x + v.y; s2 += v.x * v.x + v.y * v.y;
    }
    #pragma unroll
    for (int o = 16; o; o >>= 1) {
        s1 += __shfl_xor_sync(0xffffffffu, s1, o);
        s2 += __shfl_xor_sync(0xffffffffu, s2, o);
    }
    __shared__ float sh1[8], sh2[8];
    int wid = threadIdx.x >> 5, lane = threadIdx.x & 31;
    if (lane == 0) { sh1[wid] = s1; sh2[wid] = s2; }
    __syncthreads();
    float S1 = 0.f, S2 = 0.f;
    #pragma unroll
    for (int i = 0; i < 8; i++) { S1 += sh1[i]; S2 += sh2[i]; }
    float mean = S1 * (1.f / CIN);
    float var  = S2 * (1.f / CIN) - mean * mean;
    float inv  = rsqrtf(var + 1e-5f);
    const float2* w2 = (const float2*)w;
    const float2* b2 = (const float2*)bb;
    __half2* hr = (__half2*)(h + (size_t)row * CIN);
    for (int i = threadIdx.x; i < CIN / 2; i += 256) {
        float2 v = xr[i], ww = w2[i], bz = b2[i];
        hr[i] = __floats2half2_rn((v.x - mean) * inv * ww.x + bz.x,
                                  (v.y - mean) * inv * ww.y + bz.y);
    }
}

// ------------------------- fp16 GEMM: C = A@B^T' + bias -------------------------
// A [M,K] half row-major, Bt [N,K] half row-major (pre-transposed weights)
template<bool HALF_OUT>
__global__ __launch_bounds__(256) void gemm_f16(
        const __half* __restrict__ A, const __half* __restrict__ Bt,
        const float* __restrict__ bias, void* __restrict__ Cv,
        int M, int N, int K) {
    __shared__ __half As[128][40];
    __shared__ __half Bs[128][40];
    int tid = threadIdx.x;
    int lane = tid & 31, wid = tid >> 5;
    int wm = (wid & 3) * 32, wn = (wid >> 2) * 64;
    int bm = blockIdx.y * 128, bn = blockIdx.x * 128;
    int g = lane >> 2, tg = lane & 3;

    float acc[2][8][4];
    #pragma unroll
    for (int mt = 0; mt < 2; mt++)
        #pragma unroll
        for (int nt = 0; nt < 8; nt++)
            #pragma unroll
            for (int i = 0; i < 4; i++) acc[mt][nt][i] = 0.f;

    for (int k0 = 0; k0 < K; k0 += 32) {
        #pragma unroll
        for (int i = 0; i < 2; i++) {
            int f = tid + i * 256;          // 0..511
            int r = f >> 2, c = (f & 3) * 8;
            uint4 va = *reinterpret_cast<const uint4*>(A + (size_t)(bm + r) * K + k0 + c);
            *reinterpret_cast<uint4*>(&As[r][c]) = va;
            uint4 vb = *reinterpret_cast<const uint4*>(Bt + (size_t)(bn + r) * K + k0 + c);
            *reinterpret_cast<uint4*>(&Bs[r][c]) = vb;
        }
        __syncthreads();
        #pragma unroll
        for (int ks = 0; ks < 2; ks++) {
            uint32_t a[2][4], b[8][2];
            int co = ks * 16 + tg * 2;
            #pragma unroll
            for (int mt = 0; mt < 2; mt++) {
                int r = wm + mt * 16 + g;
                a[mt][0] = *reinterpret_cast<const uint32_t*>(&As[r][co]);
                a[mt][1] = *reinterpret_cast<const uint32_t*>(&As[r + 8][co]);
                a[mt][2] = *reinterpret_cast<const uint32_t*>(&As[r][co + 8]);
                a[mt][3] = *reinterpret_cast<const uint32_t*>(&As[r + 8][co + 8]);
            }
            #pragma unroll
            for (int nt = 0; nt < 8; nt++) {
                int r = wn + nt * 8 + g;
                b[nt][0] = *reinterpret_cast<const uint32_t*>(&Bs[r][co]);
                b[nt][1] = *reinterpret_cast<const uint32_t*>(&Bs[r][co + 8]);
            }
            #pragma unroll
            for (int mt = 0; mt < 2; mt++)
                #pragma unroll
                for (int nt = 0; nt < 8; nt++)
                    mma_f16(acc[mt][nt], a[mt], b[nt]);
        }
        __syncthreads();
    }
    #pragma unroll
    for (int mt = 0; mt < 2; mt++) {
        int r0 = bm + wm + mt * 16 + g;
        #pragma unroll
        for (int nt = 0; nt < 8; nt++) {
            int c0 = bn + wn + nt * 8 + tg * 2;
            float bz0 = bias[c0], bz1 = bias[c0 + 1];
            if (HALF_OUT) {
                __half* C = (__half*)Cv;
                *reinterpret_cast<__half2*>(C + (size_t)r0 * N + c0) =
                    __floats2half2_rn(acc[mt][nt][0] + bz0, acc[mt][nt][1] + bz1);
                *reinterpret_cast<__half2*>(C + (size_t)(r0 + 8) * N + c0) =
                    __floats2half2_rn(acc[mt][nt][2] + bz0, acc[mt][nt][3] + bz1);
            } else {
                float* C = (float*)Cv;
                C[(size_t)r0 * N + c0]           = acc[mt][nt][0] + bz0;
                C[(size_t)r0 * N + c0 + 1]       = acc[mt][nt][1] + bz1;
                C[(size_t)(r0 + 8) * N + c0]     = acc[mt][nt][2] + bz0;
                C[(size_t)(r0 + 8) * N + c0 + 1] = acc[mt][nt][3] + bz1;
            }
        }
    }
}

// ------------------------- Flash attention (causal, fp16 mma) -------------------------
// Block = (128 q-rows, head, batch), 8 warps x 16 q-rows. K tile 64 tokens.
// bufK token-major [64][72]; bufVT d-major [64][88].
__global__ __launch_bounds__(256, 2) void attn_kernel(const __half* __restrict__ qkv,
                                                      __half* __restrict__ y) {
    __shared__ __half bufK[64][72];
    __shared__ __half bufVT[64][88];
    int qt = blockIdx.x, h = blockIdx.y, b = blockIdx.z;
    int tid = threadIdx.x, lane = tid & 31, w = tid >> 5;
    int g = lane >> 2, tg = lane & 3;
    int q0 = qt * 128;
    int row0 = q0 + w * 16;
    const size_t rstr = (size_t)3 * NE;
    const __half* kbase = qkv + ((size_t)b * SEQT) * rstr + NE + h * HD;
    const __half* vbase = qkv + ((size_t)b * SEQT) * rstr + 2 * NE + h * HD;

    // Q fragments (scaled by exact power of two — no extra rounding)
    const __half2 sc2 = __float2half2_rn(0.125f);
    const __half* qbase = qkv + ((size_t)b * SEQT + row0) * rstr + h * HD;
    uint32_t qf[4][4];
    #pragma unroll
    for (int ks = 0; ks < 4; ks++) {
        int c = ks * 16 + tg * 2;
        __half2 v0 = __hmul2(*reinterpret_cast<const __half2*>(qbase + (size_t)g * rstr + c), sc2);
        __half2 v1 = __hmul2(*reinterpret_cast<const __half2*>(qbase + (size_t)(g + 8) * rstr + c), sc2);
        __half2 v2 = __hmul2(*reinterpret_cast<const __half2*>(qbase + (size_t)g * rstr + c + 8), sc2);
        __half2 v3 = __hmul2(*reinterpret_cast<const __half2*>(qbase + (size_t)(g + 8) * rstr + c + 8), sc2);
        qf[ks][0] = *reinterpret_cast<uint32_t*>(&v0);
        qf[ks][1] = *reinterpret_cast<uint32_t*>(&v1);
        qf[ks][2] = *reinterpret_cast<uint32_t*>(&v2);
        qf[ks][3] = *reinterpret_cast<uint32_t*>(&v3);
    }

    float O[8][4];
    #pragma unroll
    for (int dt = 0; dt < 8; dt++)
        #pragma unroll
        for (int i = 0; i < 4; i++) O[dt][i] = 0.f;
    float m0 = -1e30f, m1 = -1e30f, l0 = 0.f, l1 = 0.f;

    int ktmax = 2 * qt + 1;
    for (int kt = 0; kt <= ktmax; kt++) {
        int kb = kt * 64;
        // K tile: token-major, half2 coalesced, conflict-free stores
        #pragma unroll
        for (int i = 0; i < 8; i++) {
            int task = tid + i * 256;       // 0..2047
            int r = task >> 5, c2 = task & 31;
            __half2 v = *reinterpret_cast<const __half2*>(kbase + (size_t)(kb + r) * rstr + c2 * 2);
            *reinterpret_cast<__half2*>(&bufK[r][c2 * 2]) = v;
        }
        // V tile: transpose to d-major via register pair transpose
        #pragma unroll
        for (int i = 0; i < 4; i++) {
            int task = tid + i * 256;       // 0..1023
            int dp = task & 31, tp = task >> 5;
            __half2 v0 = *reinterpret_cast<const __half2*>(vbase + (size_t)(kb + 2 * tp) * rstr + dp * 2);
            __half2 v1 = *reinterpret_cast<const __half2*>(vbase + (size_t)(kb + 2 * tp + 1) * rstr + dp * 2);
            *reinterpret_cast<__half2*>(&bufVT[2 * dp][2 * tp])     = __lows2half2(v0, v1);
            *reinterpret_cast<__half2*>(&bufVT[2 * dp + 1][2 * tp]) = __highs2half2(v0, v1);
        }
        __syncthreads();

        if (kb <= row0 + 15) {
            float S[8][4];
            #pragma unroll
            for (int nt = 0; nt < 8; nt++)
                #pragma unroll
                for (int i = 0; i < 4; i++) S[nt][i] = 0.f;
            #pragma unroll
            for (int ks = 0; ks < 4; ks++) {
                int co = ks * 16 + tg * 2;
                #pragma unroll
                for (int nt = 0; nt < 8; nt++) {
                    uint32_t bk[2];
                    bk[0] = *reinterpret_cast<const uint32_t*>(&bufK[nt * 8 + g][co]);
                    bk[1] = *reinterpret_cast<const uint32_t*>(&bufK[nt * 8 + g][co + 8]);
                    mma_f16(S[nt], qf[ks], bk);
                }
            }

            if (kb + 63 > row0) {           // diagonal-straddling: elementwise mask
                int r = row0 + g;
                #pragma unroll
                for (int nt = 0; nt < 8; nt++) {
                    int c = kb + nt * 8 + tg * 2;
                    if (c     > r)     S[nt][0] = -1e30f;
                    if (c + 1 > r)     S[nt][1] = -1e30f;
                    if (c     > r + 8) S[nt][2] = -1e30f;
                    if (c + 1 > r + 8) S[nt][3] = -1e30f;
                }
            }

            float mx0 = -1e30f, mx1 = -1e30f;
            #pragma unroll
            for (int nt = 0; nt < 8; nt++) {
                mx0 = fmaxf(mx0, fmaxf(S[nt][0], S[nt][1]));
                mx1 = fmaxf(mx1, fmaxf(S[nt][2], S[nt][3]));
            }
            #pragma unroll
            for (int o = 1; o <= 2; o <<= 1) {
                mx0 = fmaxf(mx0, __shfl_xor_sync(0xffffffffu, mx0, o));
                mx1 = fmaxf(mx1, __shfl_xor_sync(0xffffffffu, mx1, o));
            }
            float nm0 = fmaxf(m0, mx0), nm1 = fmaxf(m1, mx1);
            float al0 = __expf(m0 - nm0), al1 = __expf(m1 - nm1);
            float rs0 = 0.f, rs1 = 0.f;
            #pragma unroll
            for (int nt = 0; nt < 8; nt++) {
                S[nt][0] = __expf(S[nt][0] - nm0); rs0 += S[nt][0];
                S[nt][1] = __expf(S[nt][1] - nm0); rs0 += S[nt][1];
                S[nt][2] = __expf(S[nt][2] - nm1); rs1 += S[nt][2];
                S[nt][3] = __expf(S[nt][3] - nm1); rs1 += S[nt][3];
            }
            #pragma unroll
            for (int o = 1; o <= 2; o <<= 1) {
                rs0 += __shfl_xor_sync(0xffffffffu, rs0, o);
                rs1 += __shfl_xor_sync(0xffffffffu, rs1, o);
            }
            l0 = l0 * al0 + rs0; l1 = l1 * al1 + rs1;
            m0 = nm0; m1 = nm1;
            #pragma unroll
            for (int dt = 0; dt < 8; dt++) {
                O[dt][0] *= al0; O[dt][1] *= al0; O[dt][2] *= al1; O[dt][3] *= al1;
            }

            // P·V: accumulator layout == fp16 A-fragment layout; pack in-register
            #pragma unroll
            for (int ks = 0; ks < 4; ks++) {
                __half2 p0 = __floats2half2_rn(S[2 * ks][0],     S[2 * ks][1]);
                __half2 p1 = __floats2half2_rn(S[2 * ks][2],     S[2 * ks][3]);
                __half2 p2 = __floats2half2_rn(S[2 * ks + 1][0], S[2 * ks + 1][1]);
                __half2 p3 = __floats2half2_rn(S[2 * ks + 1][2], S[2 * ks + 1][3]);
                uint32_t pa[4];
                pa[0] = *reinterpret_cast<uint32_t*>(&p0);
                pa[1] = *reinterpret_cast<uint32_t*>(&p1);
                pa[2] = *reinterpret_cast<uint32_t*>(&p2);
                pa[3] = *reinterpret_cast<uint32_t*>(&p3);
                int co = ks * 16 + tg * 2;
                #pragma unroll
                for (int dt = 0; dt < 8; dt++) {
                    uint32_t bv[2];
                    bv[0] = *reinterpret_cast<const uint32_t*>(&bufVT[dt * 8 + g][co]);
                    bv[1] = *reinterpret_cast<const uint32_t*>(&bufVT[dt * 8 + g][co + 8]);
                    mma_f16(O[dt], pa, bv);
                }
            }
        }
        __syncthreads();
    }

    float il0 = 1.f / l0, il1 = 1.f / l1;
    int r = row0 + g;
    __half* yb  = y + ((size_t)b * SEQT + r) * NE + h * HD;
    __half* yb8 = y + ((size_t)b * SEQT + r + 8) * NE + h * HD;
    #pragma unroll
    for (int dt = 0; dt < 8; dt++) {
        int c = dt * 8 + tg * 2;
        *reinterpret_cast<__half2*>(yb + c)  = __floats2half2_rn(O[dt][0] * il0, O[dt][1] * il0);
        *reinterpret_cast<__half2*>(yb8 + c) = __floats2half2_rn(O[dt][2] * il1, O[dt][3] * il1);
    }
}

// ------------------------- launch -------------------------
extern "C" void kernel_launch(void* const* d_in, const int* in_sizes, int n_in,
                              void* d_out, int out_size) {
    const float* x      = (const float*)d_in[0];
    const float* ln_w   = (const float*)d_in[1];
    const float* ln_b   = (const float*)d_in[2];
    const float* W_attn = (const float*)d_in[3];
    const float* b_attn = (const float*)d_in[4];
    const float* W_proj = (const float*)d_in[5];
    const float* b_proj = (const float*)d_in[6];
    float* out = (float*)d_out;

    __half *h, *qkv, *y, *wta, *wtp;
    cudaGetSymbolAddress((void**)&h,   g_h);
    cudaGetSymbolAddress((void**)&qkv, g_qkv);
    cudaGetSymbolAddress((void**)&y,   g_y);
    cudaGetSymbolAddress((void**)&wta, g_wta);
    cudaGetSymbolAddress((void**)&wtp, g_wtp);

    transpose_w<<<dim3(3 * NE / 32, CIN / 32), dim3(32, 8)>>>(W_attn, wta, CIN, 3 * NE);
    transpose_w<<<dim3(NE / 32, NE / 32),      dim3(32, 8)>>>(W_proj, wtp, NE, NE);
    ln_kernel<<<ROWS, 256>>>(x, ln_w, ln_b, h);
    gemm_f16<true><<<dim3(3 * NE / 128, ROWS / 128), 256>>>(h, wta, b_attn, qkv, ROWS, 3 * NE, CIN);
    attn_kernel<<<dim3(SEQT / 128, NH, BATCH), 256>>>(qkv, y);
    gemm_f16<false><<<dim3(NE / 128, ROWS / 128), 256>>>(y, wtp, b_proj, out, ROWS, NE, NE);
}

// round 9
// speedup vs baseline: 2.1125x; 1.1873x over previous
#include <cuda_runtime.h>
#include <cuda_fp16.h>
#include <cstdint>
#include <cstddef>

#define BATCH 4
#define SEQT  2048
#define CIN   1152
#define NE    1024
#define NH    16
#define HD    64
#define ROWS  (BATCH*SEQT)   // 8192

// ---- scratch (no allocations allowed) ----
__device__ __half g_h[(size_t)ROWS * CIN];          // LN output (half)
__device__ __half g_qkv[(size_t)ROWS * 3 * NE];     // QKV (half)
__device__ __half g_y[(size_t)ROWS * NE];           // attention out (half)
__device__ __half g_wta[(size_t)3 * NE * CIN];      // W_attn^T [N,K] half
__device__ __half g_wtp[(size_t)NE * NE];           // W_proj^T [N,K] half

__device__ __forceinline__ void mma_f16(float c[4], const uint32_t a[4], const uint32_t b[2]) {
    asm volatile(
        "mma.sync.aligned.m16n8k16.row.col.f32.f16.f16.f32 "
        "{%0,%1,%2,%3}, {%4,%5,%6,%7}, {%8,%9}, {%0,%1,%2,%3};\n"
        : "+f"(c[0]), "+f"(c[1]), "+f"(c[2]), "+f"(c[3])
        : "r"(a[0]), "r"(a[1]), "r"(a[2]), "r"(a[3]), "r"(b[0]), "r"(b[1]));
}

__device__ __forceinline__ uint32_t smem_u32(const void* p) {
    return (uint32_t)__cvta_generic_to_shared(p);
}
#define CP_ASYNC16(dst, src) \
    asm volatile("cp.async.cg.shared.global [%0], [%1], 16;\n" :: "r"(dst), "l"(src))
#define CP_COMMIT() asm volatile("cp.async.commit_group;\n")
#define CP_WAIT1()  asm volatile("cp.async.wait_group 1;\n")
#define LDSM_X4(r0, r1, r2, r3, addr) \
    asm volatile("ldmatrix.sync.aligned.m8n8.x4.shared.b16 {%0,%1,%2,%3}, [%4];" \
                 : "=r"(r0), "=r"(r1), "=r"(r2), "=r"(r3) : "r"(addr))

// ---------------- weight transpose + half convert: wT[n][k] = (half)W[k][n] ----------------
__global__ void transpose_w(const float* __restrict__ W, __half* __restrict__ wT, int K, int N) {
    __shared__ float t[32][33];
    int n0 = blockIdx.x * 32, k0 = blockIdx.y * 32;
    #pragma unroll
    for (int i = threadIdx.y; i < 32; i += 8)
        t[i][threadIdx.x] = W[(size_t)(k0 + i) * N + n0 + threadIdx.x];
    __syncthreads();
    #pragma unroll
    for (int i = threadIdx.y; i < 32; i += 8)
        wT[(size_t)(n0 + i) * K + k0 + threadIdx.x] = __float2half_rn(t[threadIdx.x][i]);
}

// ------------------------- LayerNorm (writes half) -------------------------
__global__ void ln_kernel(const float* __restrict__ x, const float* __restrict__ w,
                          const float* __restrict__ bb, __half* __restrict__ h) {
    int row = blockIdx.x;
    const float2* xr = (const float2*)(x + (size_t)row * CIN);   // 576 float2
    float s1 = 0.f, s2 = 0.f;
    for (int i = threadIdx.x; i < CIN / 2; i += 256) {
        float2 v = xr[i];
        s1 += v.x + v.y; s2 += v.x * v.x + v.y * v.y;
    }
    #pragma unroll
    for (int o = 16; o; o >>= 1) {
        s1 += __shfl_xor_sync(0xffffffffu, s1, o);
        s2 += __shfl_xor_sync(0xffffffffu, s2, o);
    }
    __shared__ float sh1[8], sh2[8];
    int wid = threadIdx.x >> 5, lane = threadIdx.x & 31;
    if (lane == 0) { sh1[wid] = s1; sh2[wid] = s2; }
    __syncthreads();
    float S1 = 0.f, S2 = 0.f;
    #pragma unroll
    for (int i = 0; i < 8; i++) { S1 += sh1[i]; S2 += sh2[i]; }
    float mean = S1 * (1.f / CIN);
    float var  = S2 * (1.f / CIN) - mean * mean;
    float inv  = rsqrtf(var + 1e-5f);
    const float2* w2 = (const float2*)w;
    const float2* b2 = (const float2*)bb;
    __half2* hr = (__half2*)(h + (size_t)row * CIN);
    for (int i = threadIdx.x; i < CIN / 2; i += 256) {
        float2 v = xr[i], ww = w2[i], bz = b2[i];
        hr[i] = __floats2half2_rn((v.x - mean) * inv * ww.x + bz.x,
                                  (v.y - mean) * inv * ww.y + bz.y);
    }
}

// ------------------------- fp16 GEMM: C = A@Bt^T + bias -------------------------
// A [M,K] half row-major, Bt [N,K] half row-major. 2-stage cp.async + ldmatrix.
template<bool HALF_OUT>
__global__ __launch_bounds__(256) void gemm_f16(
        const __half* __restrict__ A, const __half* __restrict__ Bt,
        const float* __restrict__ bias, void* __restrict__ Cv,
        int M, int N, int K) {
    __shared__ __half As[2][128][40];
    __shared__ __half Bs[2][128][40];
    int tid = threadIdx.x;
    int lane = tid & 31, wid = tid >> 5;
    int wm = (wid & 3) * 32, wn = (wid >> 2) * 64;
    int bm = blockIdx.y * 128, bn = blockIdx.x * 128;
    int g = lane >> 2, tg = lane & 3;

    float acc[2][8][4];
    #pragma unroll
    for (int mt = 0; mt < 2; mt++)
        #pragma unroll
        for (int nt = 0; nt < 8; nt++)
            #pragma unroll
            for (int i = 0; i < 4; i++) acc[mt][nt][i] = 0.f;

    const __half* Abase = A + (size_t)bm * K;
    const __half* Bbase = Bt + (size_t)bn * K;
    int ktiles = K >> 5;

    // ldmatrix per-lane source coordinates (fragment layouts identical to mma spec)
    int a_row = (lane & 7) + ((lane >> 3) & 1) * 8;   // + wm + mt*16
    int a_col = (lane >> 4) * 8;                      // + ks*16
    int b_row = (lane & 7) + (lane >> 4) * 8;         // + wn + ntp*8
    int b_col = ((lane >> 3) & 1) * 8;                // + ks*16

    // prologue: stage 0
    #pragma unroll
    for (int i = 0; i < 2; i++) {
        int f = tid + i * 256;
        int r = f >> 2, c = (f & 3) * 8;
        CP_ASYNC16(smem_u32(&As[0][r][c]), Abase + (size_t)r * K + c);
        CP_ASYNC16(smem_u32(&Bs[0][r][c]), Bbase + (size_t)r * K + c);
    }
    CP_COMMIT();

    for (int it = 0; it < ktiles; it++) {
        int cur = it & 1;
        if (it + 1 < ktiles) {
            int k0 = (it + 1) << 5;
            #pragma unroll
            for (int i = 0; i < 2; i++) {
                int f = tid + i * 256;
                int r = f >> 2, c = (f & 3) * 8;
                CP_ASYNC16(smem_u32(&As[cur ^ 1][r][c]), Abase + (size_t)r * K + k0 + c);
                CP_ASYNC16(smem_u32(&Bs[cur ^ 1][r][c]), Bbase + (size_t)r * K + k0 + c);
            }
        }
        CP_COMMIT();
        CP_WAIT1();
        __syncthreads();

        #pragma unroll
        for (int ks = 0; ks < 2; ks++) {
            uint32_t a[2][4], b[8][2];
            #pragma unroll
            for (int mt = 0; mt < 2; mt++) {
                uint32_t addr = smem_u32(&As[cur][wm + mt * 16 + a_row][ks * 16 + a_col]);
                LDSM_X4(a[mt][0], a[mt][1], a[mt][2], a[mt][3], addr);
            }
            #pragma unroll
            for (int ntp = 0; ntp < 8; ntp += 2) {
                uint32_t addr = smem_u32(&Bs[cur][wn + ntp * 8 + b_row][ks * 16 + b_col]);
                LDSM_X4(b[ntp][0], b[ntp][1], b[ntp + 1][0], b[ntp + 1][1], addr);
            }
            #pragma unroll
            for (int mt = 0; mt < 2; mt++)
                #pragma unroll
                for (int nt = 0; nt < 8; nt++)
                    mma_f16(acc[mt][nt], a[mt], b[nt]);
        }
        __syncthreads();
    }

    #pragma unroll
    for (int mt = 0; mt < 2; mt++) {
        int r0 = bm + wm + mt * 16 + g;
        #pragma unroll
        for (int nt = 0; nt < 8; nt++) {
            int c0 = bn + wn + nt * 8 + tg * 2;
            float bz0 = bias[c0], bz1 = bias[c0 + 1];
            if (HALF_OUT) {
                __half* C = (__half*)Cv;
                *reinterpret_cast<__half2*>(C + (size_t)r0 * N + c0) =
                    __floats2half2_rn(acc[mt][nt][0] + bz0, acc[mt][nt][1] + bz1);
                *reinterpret_cast<__half2*>(C + (size_t)(r0 + 8) * N + c0) =
                    __floats2half2_rn(acc[mt][nt][2] + bz0, acc[mt][nt][3] + bz1);
            } else {
                float* C = (float*)Cv;
                C[(size_t)r0 * N + c0]           = acc[mt][nt][0] + bz0;
                C[(size_t)r0 * N + c0 + 1]       = acc[mt][nt][1] + bz1;
                C[(size_t)(r0 + 8) * N + c0]     = acc[mt][nt][2] + bz0;
                C[(size_t)(r0 + 8) * N + c0 + 1] = acc[mt][nt][3] + bz1;
            }
        }
    }
}

// ------------------------- Flash attention (causal, fp16 mma) -------------------------
// Block = (128 q-rows, head, batch), 8 warps x 16 q-rows. K tile 64 tokens.
__global__ __launch_bounds__(256, 2) void attn_kernel(const __half* __restrict__ qkv,
                                                      __half* __restrict__ y) {
    __shared__ __half bufK[64][72];
    __shared__ __half bufVT[64][88];
    int qt = blockIdx.x, h = blockIdx.y, b = blockIdx.z;
    int tid = threadIdx.x, lane = tid & 31, w = tid >> 5;
    int g = lane >> 2, tg = lane & 3;
    int q0 = qt * 128;
    int row0 = q0 + w * 16;
    const size_t rstr = (size_t)3 * NE;
    const __half* kbase = qkv + ((size_t)b * SEQT) * rstr + NE + h * HD;
    const __half* vbase = qkv + ((size_t)b * SEQT) * rstr + 2 * NE + h * HD;

    const __half2 sc2 = __float2half2_rn(0.125f);
    const __half* qbase = qkv + ((size_t)b * SEQT + row0) * rstr + h * HD;
    uint32_t qf[4][4];
    #pragma unroll
    for (int ks = 0; ks < 4; ks++) {
        int c = ks * 16 + tg * 2;
        __half2 v0 = __hmul2(*reinterpret_cast<const __half2*>(qbase + (size_t)g * rstr + c), sc2);
        __half2 v1 = __hmul2(*reinterpret_cast<const __half2*>(qbase + (size_t)(g + 8) * rstr + c), sc2);
        __half2 v2 = __hmul2(*reinterpret_cast<const __half2*>(qbase + (size_t)g * rstr + c + 8), sc2);
        __half2 v3 = __hmul2(*reinterpret_cast<const __half2*>(qbase + (size_t)(g + 8) * rstr + c + 8), sc2);
        qf[ks][0] = *reinterpret_cast<uint32_t*>(&v0);
        qf[ks][1] = *reinterpret_cast<uint32_t*>(&v1);
        qf[ks][2] = *reinterpret_cast<uint32_t*>(&v2);
        qf[ks][3] = *reinterpret_cast<uint32_t*>(&v3);
    }

    float O[8][4];
    #pragma unroll
    for (int dt = 0; dt < 8; dt++)
        #pragma unroll
        for (int i = 0; i < 4; i++) O[dt][i] = 0.f;
    float m0 = -1e30f, m1 = -1e30f, l0 = 0.f, l1 = 0.f;

    int ktmax = 2 * qt + 1;
    for (int kt = 0; kt <= ktmax; kt++) {
        int kb = kt * 64;
        #pragma unroll
        for (int i = 0; i < 8; i++) {
            int task = tid + i * 256;
            int r = task >> 5, c2 = task & 31;
            __half2 v = *reinterpret_cast<const __half2*>(kbase + (size_t)(kb + r) * rstr + c2 * 2);
            *reinterpret_cast<__half2*>(&bufK[r][c2 * 2]) = v;
        }
        #pragma unroll
        for (int i = 0; i < 4; i++) {
            int task = tid + i * 256;
            int dp = task & 31, tp = task >> 5;
            __half2 v0 = *reinterpret_cast<const __half2*>(vbase + (size_t)(kb + 2 * tp) * rstr + dp * 2);
            __half2 v1 = *reinterpret_cast<const __half2*>(vbase + (size_t)(kb + 2 * tp + 1) * rstr + dp * 2);
            *reinterpret_cast<__half2*>(&bufVT[2 * dp][2 * tp])     = __lows2half2(v0, v1);
            *reinterpret_cast<__half2*>(&bufVT[2 * dp + 1][2 * tp]) = __highs2half2(v0, v1);
        }
        __syncthreads();

        if (kb <= row0 + 15) {
            float S[8][4];
            #pragma unroll
            for (int nt = 0; nt < 8; nt++)
                #pragma unroll
                for (int i = 0; i < 4; i++) S[nt][i] = 0.f;
            #pragma unroll
            for (int ks = 0; ks < 4; ks++) {
                int co = ks * 16 + tg * 2;
                #pragma unroll
                for (int nt = 0; nt < 8; nt++) {
                    uint32_t bk[2];
                    bk[0] = *reinterpret_cast<const uint32_t*>(&bufK[nt * 8 + g][co]);
                    bk[1] = *reinterpret_cast<const uint32_t*>(&bufK[nt * 8 + g][co + 8]);
                    mma_f16(S[nt], qf[ks], bk);
                }
            }

            if (kb + 63 > row0) {
                int r = row0 + g;
                #pragma unroll
                for (int nt = 0; nt < 8; nt++) {
                    int c = kb + nt * 8 + tg * 2;
                    if (c     > r)     S[nt][0] = -1e30f;
                    if (c + 1 > r)     S[nt][1] = -1e30f;
                    if (c     > r + 8) S[nt][2] = -1e30f;
                    if (c + 1 > r + 8) S[nt][3] = -1e30f;
                }
            }

            float mx0 = -1e30f, mx1 = -1e30f;
            #pragma unroll
            for (int nt = 0; nt < 8; nt++) {
                mx0 = fmaxf(mx0, fmaxf(S[nt][0], S[nt][1]));
                mx1 = fmaxf(mx1, fmaxf(S[nt][2], S[nt][3]));
            }
            #pragma unroll
            for (int o = 1; o <= 2; o <<= 1) {
                mx0 = fmaxf(mx0, __shfl_xor_sync(0xffffffffu, mx0, o));
                mx1 = fmaxf(mx1, __shfl_xor_sync(0xffffffffu, mx1, o));
            }
            float nm0 = fmaxf(m0, mx0), nm1 = fmaxf(m1, mx1);
            float al0 = __expf(m0 - nm0), al1 = __expf(m1 - nm1);
            float rs0 = 0.f, rs1 = 0.f;
            #pragma unroll
            for (int nt = 0; nt < 8; nt++) {
                S[nt][0] = __expf(S[nt][0] - nm0); rs0 += S[nt][0];
                S[nt][1] = __expf(S[nt][1] - nm0); rs0 += S[nt][1];
                S[nt][2] = __expf(S[nt][2] - nm1); rs1 += S[nt][2];
                S[nt][3] = __expf(S[nt][3] - nm1); rs1 += S[nt][3];
            }
            #pragma unroll
            for (int o = 1; o <= 2; o <<= 1) {
                rs0 += __shfl_xor_sync(0xffffffffu, rs0, o);
                rs1 += __shfl_xor_sync(0xffffffffu, rs1, o);
            }
            l0 = l0 * al0 + rs0; l1 = l1 * al1 + rs1;
            m0 = nm0; m1 = nm1;
            #pragma unroll
            for (int dt = 0; dt < 8; dt++) {
                O[dt][0] *= al0; O[dt][1] *= al0; O[dt][2] *= al1; O[dt][3] *= al1;
            }

            #pragma unroll
            for (int ks = 0; ks < 4; ks++) {
                __half2 p0 = __floats2half2_rn(S[2 * ks][0],     S[2 * ks][1]);
                __half2 p1 = __floats2half2_rn(S[2 * ks][2],     S[2 * ks][3]);
                __half2 p2 = __floats2half2_rn(S[2 * ks + 1][0], S[2 * ks + 1][1]);
                __half2 p3 = __floats2half2_rn(S[2 * ks + 1][2], S[2 * ks + 1][3]);
                uint32_t pa[4];
                pa[0] = *reinterpret_cast<uint32_t*>(&p0);
                pa[1] = *reinterpret_cast<uint32_t*>(&p1);
                pa[2] = *reinterpret_cast<uint32_t*>(&p2);
                pa[3] = *reinterpret_cast<uint32_t*>(&p3);
                int co = ks * 16 + tg * 2;
                #pragma unroll
                for (int dt = 0; dt < 8; dt++) {
                    uint32_t bv[2];
                    bv[0] = *reinterpret_cast<const uint32_t*>(&bufVT[dt * 8 + g][co]);
                    bv[1] = *reinterpret_cast<const uint32_t*>(&bufVT[dt * 8 + g][co + 8]);
                    mma_f16(O[dt], pa, bv);
                }
            }
        }
        __syncthreads();
    }

    float il0 = 1.f / l0, il1 = 1.f / l1;
    int r = row0 + g;
    __half* yb  = y + ((size_t)b * SEQT + r) * NE + h * HD;
    __half* yb8 = y + ((size_t)b * SEQT + r + 8) * NE + h * HD;
    #pragma unroll
    for (int dt = 0; dt < 8; dt++) {
        int c = dt * 8 + tg * 2;
        *reinterpret_cast<__half2*>(yb + c)  = __floats2half2_rn(O[dt][0] * il0, O[dt][1] * il0);
        *reinterpret_cast<__half2*>(yb8 + c) = __floats2half2_rn(O[dt][2] * il1, O[dt][3] * il1);
    }
}

// ------------------------- launch -------------------------
extern "C" void kernel_launch(void* const* d_in, const int* in_sizes, int n_in,
                              void* d_out, int out_size) {
    const float* x      = (const float*)d_in[0];
    const float* ln_w   = (const float*)d_in[1];
    const float* ln_b   = (const float*)d_in[2];
    const float* W_attn = (const float*)d_in[3];
    const float* b_attn = (const float*)d_in[4];
    const float* W_proj = (const float*)d_in[5];
    const float* b_proj = (const float*)d_in[6];
    float* out = (float*)d_out;

    __half *h, *qkv, *y, *wta, *wtp;
    cudaGetSymbolAddress((void**)&h,   g_h);
    cudaGetSymbolAddress((void**)&qkv, g_qkv);
    cudaGetSymbolAddress((void**)&y,   g_y);
    cudaGetSymbolAddress((void**)&wta, g_wta);
    cudaGetSymbolAddress((void**)&wtp, g_wtp);

    transpose_w<<<dim3(3 * NE / 32, CIN / 32), dim3(32, 8)>>>(W_attn, wta, CIN, 3 * NE);
    transpose_w<<<dim3(NE / 32, NE / 32),      dim3(32, 8)>>>(W_proj, wtp, NE, NE);
    ln_kernel<<<ROWS, 256>>>(x, ln_w, ln_b, h);
    gemm_f16<true><<<dim3(3 * NE / 128, ROWS / 128), 256>>>(h, wta, b_attn, qkv, ROWS, 3 * NE, CIN);
    attn_kernel<<<dim3(SEQT / 128, NH, BATCH), 256>>>(qkv, y);
    gemm_f16<false><<<dim3(NE / 128, ROWS / 128), 256>>>(y, wtp, b_proj, out, ROWS, NE, NE);
}

// round 10
// speedup vs baseline: 2.2012x; 1.0420x over previous
#include <cuda_runtime.h>
#include <cuda_fp16.h>
#include <cstdint>
#include <cstddef>

#define BATCH 4
#define SEQT  2048
#define CIN   1152
#define NE    1024
#define NH    16
#define HD    64
#define ROWS  (BATCH*SEQT)   // 8192

// ---- scratch (no allocations allowed) ----
__device__ __half g_h[(size_t)ROWS * CIN];          // LN output (half)
__device__ __half g_qkv[(size_t)ROWS * 3 * NE];     // QKV (half)
__device__ __half g_y[(size_t)ROWS * NE];           // attention out (half)
__device__ __half g_wta[(size_t)3 * NE * CIN];      // W_attn^T [N,K] half
__device__ __half g_wtp[(size_t)NE * NE];           // W_proj^T [N,K] half

__device__ __forceinline__ void mma_f16(float c[4], const uint32_t a[4], const uint32_t b[2]) {
    asm volatile(
        "mma.sync.aligned.m16n8k16.row.col.f32.f16.f16.f32 "
        "{%0,%1,%2,%3}, {%4,%5,%6,%7}, {%8,%9}, {%0,%1,%2,%3};\n"
        : "+f"(c[0]), "+f"(c[1]), "+f"(c[2]), "+f"(c[3])
        : "r"(a[0]), "r"(a[1]), "r"(a[2]), "r"(a[3]), "r"(b[0]), "r"(b[1]));
}

__device__ __forceinline__ uint32_t smem_u32(const void* p) {
    return (uint32_t)__cvta_generic_to_shared(p);
}
#define CP_ASYNC16(dst, src) \
    asm volatile("cp.async.cg.shared.global [%0], [%1], 16;\n" :: "r"(dst), "l"(src))
#define CP_COMMIT() asm volatile("cp.async.commit_group;\n")
#define CP_WAIT1()  asm volatile("cp.async.wait_group 1;\n")
#define CP_WAIT0()  asm volatile("cp.async.wait_group 0;\n")
#define LDSM_X4(r0, r1, r2, r3, addr) \
    asm volatile("ldmatrix.sync.aligned.m8n8.x4.shared.b16 {%0,%1,%2,%3}, [%4];" \
                 : "=r"(r0), "=r"(r1), "=r"(r2), "=r"(r3) : "r"(addr))

// ---------------- weight transpose + half convert: wT[n][k] = (half)W[k][n] ----------------
__global__ void transpose_w(const float* __restrict__ W, __half* __restrict__ wT, int K, int N) {
    __shared__ float t[32][33];
    int n0 = blockIdx.x * 32, k0 = blockIdx.y * 32;
    #pragma unroll
    for (int i = threadIdx.y; i < 32; i += 8)
        t[i][threadIdx.x] = W[(size_t)(k0 + i) * N + n0 + threadIdx.x];
    __syncthreads();
    #pragma unroll
    for (int i = threadIdx.y; i < 32; i += 8)
        wT[(size_t)(n0 + i) * K + k0 + threadIdx.x] = __float2half_rn(t[threadIdx.x][i]);
}

// ------------------------- LayerNorm (writes half) -------------------------
__global__ void ln_kernel(const float* __restrict__ x, const float* __restrict__ w,
                          const float* __restrict__ bb, __half* __restrict__ h) {
    int row = blockIdx.x;
    const float2* xr = (const float2*)(x + (size_t)row * CIN);
    float s1 = 0.f, s2 = 0.f;
    for (int i = threadIdx.x; i < CIN / 2; i += 256) {
        float2 v = xr[i];
        s1 += v.x + v.y; s2 += v.x * v.x + v.y * v.y;
    }
    #pragma unroll
    for (int o = 16; o; o >>= 1) {
        s1 += __shfl_xor_sync(0xffffffffu, s1, o);
        s2 += __shfl_xor_sync(0xffffffffu, s2, o);
    }
    __shared__ float sh1[8], sh2[8];
    int wid = threadIdx.x >> 5, lane = threadIdx.x & 31;
    if (lane == 0) { sh1[wid] = s1; sh2[wid] = s2; }
    __syncthreads();
    float S1 = 0.f, S2 = 0.f;
    #pragma unroll
    for (int i = 0; i < 8; i++) { S1 += sh1[i]; S2 += sh2[i]; }
    float mean = S1 * (1.f / CIN);
    float var  = S2 * (1.f / CIN) - mean * mean;
    float inv  = rsqrtf(var + 1e-5f);
    const float2* w2 = (const float2*)w;
    const float2* b2 = (const float2*)bb;
    __half2* hr = (__half2*)(h + (size_t)row * CIN);
    for (int i = threadIdx.x; i < CIN / 2; i += 256) {
        float2 v = xr[i], ww = w2[i], bz = b2[i];
        hr[i] = __floats2half2_rn((v.x - mean) * inv * ww.x + bz.x,
                                  (v.y - mean) * inv * ww.y + bz.y);
    }
}

// ------------------------- fp16 GEMM: C = A@Bt^T + bias -------------------------
// A [M,K] half row-major, Bt [N,K] half row-major. 3-stage cp.async, 1 sync/iter.
template<bool HALF_OUT>
__global__ __launch_bounds__(256) void gemm_f16(
        const __half* __restrict__ A, const __half* __restrict__ Bt,
        const float* __restrict__ bias, void* __restrict__ Cv,
        int M, int N, int K) {
    __shared__ __half As[3][128][40];
    __shared__ __half Bs[3][128][40];
    int tid = threadIdx.x;
    int lane = tid & 31, wid = tid >> 5;
    int wm = (wid & 3) * 32, wn = (wid >> 2) * 64;
    int bm = blockIdx.y * 128, bn = blockIdx.x * 128;
    int g = lane >> 2, tg = lane & 3;

    float acc[2][8][4];
    #pragma unroll
    for (int mt = 0; mt < 2; mt++)
        #pragma unroll
        for (int nt = 0; nt < 8; nt++)
            #pragma unroll
            for (int i = 0; i < 4; i++) acc[mt][nt][i] = 0.f;

    const __half* Abase = A + (size_t)bm * K;
    const __half* Bbase = Bt + (size_t)bn * K;
    int ktiles = K >> 5;

    int a_row = (lane & 7) + ((lane >> 3) & 1) * 8;
    int a_col = (lane >> 4) * 8;
    int b_row = (lane & 7) + (lane >> 4) * 8;
    int b_col = ((lane >> 3) & 1) * 8;

    int lr = tid >> 2, lc = (tid & 3) * 8;       // this thread's load coords
    int lr2 = (tid + 256) >> 2, lc2 = ((tid + 256) & 3) * 8;

    // prologue: tiles 0 and 1
    #pragma unroll
    for (int s = 0; s < 2; s++) {
        int k0 = s << 5;
        CP_ASYNC16(smem_u32(&As[s][lr][lc]),  Abase + (size_t)lr * K + k0 + lc);
        CP_ASYNC16(smem_u32(&Bs[s][lr][lc]),  Bbase + (size_t)lr * K + k0 + lc);
        CP_ASYNC16(smem_u32(&As[s][lr2][lc2]), Abase + (size_t)lr2 * K + k0 + lc2);
        CP_ASYNC16(smem_u32(&Bs[s][lr2][lc2]), Bbase + (size_t)lr2 * K + k0 + lc2);
        CP_COMMIT();
    }

    for (int it = 0; it < ktiles; it++) {
        CP_WAIT1();
        __syncthreads();
        int cur = it % 3;

        #pragma unroll
        for (int ks = 0; ks < 2; ks++) {
            uint32_t a[2][4], b[8][2];
            #pragma unroll
            for (int mt = 0; mt < 2; mt++) {
                uint32_t addr = smem_u32(&As[cur][wm + mt * 16 + a_row][ks * 16 + a_col]);
                LDSM_X4(a[mt][0], a[mt][1], a[mt][2], a[mt][3], addr);
            }
            #pragma unroll
            for (int ntp = 0; ntp < 8; ntp += 2) {
                uint32_t addr = smem_u32(&Bs[cur][wn + ntp * 8 + b_row][ks * 16 + b_col]);
                LDSM_X4(b[ntp][0], b[ntp][1], b[ntp + 1][0], b[ntp + 1][1], addr);
            }
            #pragma unroll
            for (int mt = 0; mt < 2; mt++)
                #pragma unroll
                for (int nt = 0; nt < 8; nt++)
                    mma_f16(acc[mt][nt], a[mt], b[nt]);
        }

        int nt_ = it + 2;
        if (nt_ < ktiles) {
            int s = nt_ % 3, k0 = nt_ << 5;
            CP_ASYNC16(smem_u32(&As[s][lr][lc]),  Abase + (size_t)lr * K + k0 + lc);
            CP_ASYNC16(smem_u32(&Bs[s][lr][lc]),  Bbase + (size_t)lr * K + k0 + lc);
            CP_ASYNC16(smem_u32(&As[s][lr2][lc2]), Abase + (size_t)lr2 * K + k0 + lc2);
            CP_ASYNC16(smem_u32(&Bs[s][lr2][lc2]), Bbase + (size_t)lr2 * K + k0 + lc2);
        }
        CP_COMMIT();
    }

    #pragma unroll
    for (int mt = 0; mt < 2; mt++) {
        int r0 = bm + wm + mt * 16 + g;
        #pragma unroll
        for (int nt = 0; nt < 8; nt++) {
            int c0 = bn + wn + nt * 8 + tg * 2;
            float bz0 = bias[c0], bz1 = bias[c0 + 1];
            if (HALF_OUT) {
                __half* C = (__half*)Cv;
                *reinterpret_cast<__half2*>(C + (size_t)r0 * N + c0) =
                    __floats2half2_rn(acc[mt][nt][0] + bz0, acc[mt][nt][1] + bz1);
                *reinterpret_cast<__half2*>(C + (size_t)(r0 + 8) * N + c0) =
                    __floats2half2_rn(acc[mt][nt][2] + bz0, acc[mt][nt][3] + bz1);
            } else {
                float* C = (float*)Cv;
                C[(size_t)r0 * N + c0]           = acc[mt][nt][0] + bz0;
                C[(size_t)r0 * N + c0 + 1]       = acc[mt][nt][1] + bz1;
                C[(size_t)(r0 + 8) * N + c0]     = acc[mt][nt][2] + bz0;
                C[(size_t)(r0 + 8) * N + c0 + 1] = acc[mt][nt][3] + bz1;
            }
        }
    }
}

// ------------------------- Flash attention (causal, fp16 mma) -------------------------
// Block = (128 q-rows, head, batch), 8 warps x 16 q-rows.
// Outer tile = 128 tokens (cp.async K + register-transposed V), two 64-token
// inner halves reusing the S[8][4] register budget. One sync pair per 128 tokens.
__global__ __launch_bounds__(256, 2) void attn_kernel(const __half* __restrict__ qkv,
                                                      __half* __restrict__ y) {
    __shared__ __half bufK[128][72];
    __shared__ __half bufVT[64][152];   // word stride 76 ≡ 12 mod 32: PV reads conflict-free
    int qt = blockIdx.x, h = blockIdx.y, b = blockIdx.z;
    int tid = threadIdx.x, lane = tid & 31, w = tid >> 5;
    int g = lane >> 2, tg = lane & 3;
    int q0 = qt * 128;
    int row0 = q0 + w * 16;
    const size_t rstr = (size_t)3 * NE;
    const __half* kbase = qkv + ((size_t)b * SEQT) * rstr + NE + h * HD;
    const __half* vbase = qkv + ((size_t)b * SEQT) * rstr + 2 * NE + h * HD;

    const __half2 sc2 = __float2half2_rn(0.125f);
    const __half* qbase = qkv + ((size_t)b * SEQT + row0) * rstr + h * HD;
    uint32_t qf[4][4];
    #pragma unroll
    for (int ks = 0; ks < 4; ks++) {
        int c = ks * 16 + tg * 2;
        __half2 v0 = __hmul2(*reinterpret_cast<const __half2*>(qbase + (size_t)g * rstr + c), sc2);
        __half2 v1 = __hmul2(*reinterpret_cast<const __half2*>(qbase + (size_t)(g + 8) * rstr + c), sc2);
        __half2 v2 = __hmul2(*reinterpret_cast<const __half2*>(qbase + (size_t)g * rstr + c + 8), sc2);
        __half2 v3 = __hmul2(*reinterpret_cast<const __half2*>(qbase + (size_t)(g + 8) * rstr + c + 8), sc2);
        qf[ks][0] = *reinterpret_cast<uint32_t*>(&v0);
        qf[ks][1] = *reinterpret_cast<uint32_t*>(&v1);
        qf[ks][2] = *reinterpret_cast<uint32_t*>(&v2);
        qf[ks][3] = *reinterpret_cast<uint32_t*>(&v3);
    }

    float O[8][4];
    #pragma unroll
    for (int dt = 0; dt < 8; dt++)
        #pragma unroll
        for (int i = 0; i < 4; i++) O[dt][i] = 0.f;
    float m0 = -1e30f, m1 = -1e30f, l0 = 0.f, l1 = 0.f;

    int ntile = qt + 1;                 // 128-token tiles
    for (int kt0 = 0; kt0 < ntile; kt0++) {
        int kb0 = kt0 * 128;
        // K tile: cp.async, issued first (hidden behind V transpose work)
        #pragma unroll
        for (int i = 0; i < 4; i++) {
            int task = tid + i * 256;       // 0..1023
            int r = task >> 3, c = task & 7;
            CP_ASYNC16(smem_u32(&bufK[r][c * 8]), kbase + (size_t)(kb0 + r) * rstr + c * 8);
        }
        CP_COMMIT();
        // V tile: register pair-transpose to d-major
        #pragma unroll
        for (int i = 0; i < 8; i++) {
            int task = tid + i * 256;       // 0..2047
            int dp = task & 31, tp = task >> 5;   // tp 0..63 token-pairs
            __half2 v0 = *reinterpret_cast<const __half2*>(vbase + (size_t)(kb0 + 2 * tp) * rstr + dp * 2);
            __half2 v1 = *reinterpret_cast<const __half2*>(vbase + (size_t)(kb0 + 2 * tp + 1) * rstr + dp * 2);
            *reinterpret_cast<__half2*>(&bufVT[2 * dp][2 * tp])     = __lows2half2(v0, v1);
            *reinterpret_cast<__half2*>(&bufVT[2 * dp + 1][2 * tp]) = __highs2half2(v0, v1);
        }
        CP_WAIT0();
        __syncthreads();

        #pragma unroll
        for (int hf = 0; hf < 2; hf++) {
            int kb = kb0 + hf * 64;
            if (kb > row0 + 15) break;       // warp-uniform causal skip
            int ro = hf * 64;                // row/col offset within buffers

            float S[8][4];
            #pragma unroll
            for (int nt = 0; nt < 8; nt++)
                #pragma unroll
                for (int i = 0; i < 4; i++) S[nt][i] = 0.f;
            #pragma unroll
            for (int ks = 0; ks < 4; ks++) {
                int co = ks * 16 + tg * 2;
                #pragma unroll
                for (int nt = 0; nt < 8; nt++) {
                    uint32_t bk[2];
                    bk[0] = *reinterpret_cast<const uint32_t*>(&bufK[ro + nt * 8 + g][co]);
                    bk[1] = *reinterpret_cast<const uint32_t*>(&bufK[ro + nt * 8 + g][co + 8]);
                    mma_f16(S[nt], qf[ks], bk);
                }
            }

            if (kb + 63 > row0) {
                int r = row0 + g;
                #pragma unroll
                for (int nt = 0; nt < 8; nt++) {
                    int c = kb + nt * 8 + tg * 2;
                    if (c     > r)     S[nt][0] = -1e30f;
                    if (c + 1 > r)     S[nt][1] = -1e30f;
                    if (c     > r + 8) S[nt][2] = -1e30f;
                    if (c + 1 > r + 8) S[nt][3] = -1e30f;
                }
            }

            float mx0 = -1e30f, mx1 = -1e30f;
            #pragma unroll
            for (int nt = 0; nt < 8; nt++) {
                mx0 = fmaxf(mx0, fmaxf(S[nt][0], S[nt][1]));
                mx1 = fmaxf(mx1, fmaxf(S[nt][2], S[nt][3]));
            }
            #pragma unroll
            for (int o = 1; o <= 2; o <<= 1) {
                mx0 = fmaxf(mx0, __shfl_xor_sync(0xffffffffu, mx0, o));
                mx1 = fmaxf(mx1, __shfl_xor_sync(0xffffffffu, mx1, o));
            }
            float nm0 = fmaxf(m0, mx0), nm1 = fmaxf(m1, mx1);
            float al0 = __expf(m0 - nm0), al1 = __expf(m1 - nm1);
            float rs0 = 0.f, rs1 = 0.f;
            #pragma unroll
            for (int nt = 0; nt < 8; nt++) {
                S[nt][0] = __expf(S[nt][0] - nm0); rs0 += S[nt][0];
                S[nt][1] = __expf(S[nt][1] - nm0); rs0 += S[nt][1];
                S[nt][2] = __expf(S[nt][2] - nm1); rs1 += S[nt][2];
                S[nt][3] = __expf(S[nt][3] - nm1); rs1 += S[nt][3];
            }
            #pragma unroll
            for (int o = 1; o <= 2; o <<= 1) {
                rs0 += __shfl_xor_sync(0xffffffffu, rs0, o);
                rs1 += __shfl_xor_sync(0xffffffffu, rs1, o);
            }
            l0 = l0 * al0 + rs0; l1 = l1 * al1 + rs1;
            m0 = nm0; m1 = nm1;
            #pragma unroll
            for (int dt = 0; dt < 8; dt++) {
                O[dt][0] *= al0; O[dt][1] *= al0; O[dt][2] *= al1; O[dt][3] *= al1;
            }

            #pragma unroll
            for (int ks = 0; ks < 4; ks++) {
                __half2 p0 = __floats2half2_rn(S[2 * ks][0],     S[2 * ks][1]);
                __half2 p1 = __floats2half2_rn(S[2 * ks][2],     S[2 * ks][3]);
                __half2 p2 = __floats2half2_rn(S[2 * ks + 1][0], S[2 * ks + 1][1]);
                __half2 p3 = __floats2half2_rn(S[2 * ks + 1][2], S[2 * ks + 1][3]);
                uint32_t pa[4];
                pa[0] = *reinterpret_cast<uint32_t*>(&p0);
                pa[1] = *reinterpret_cast<uint32_t*>(&p1);
                pa[2] = *reinterpret_cast<uint32_t*>(&p2);
                pa[3] = *reinterpret_cast<uint32_t*>(&p3);
                int co = ro + ks * 16 + tg * 2;
                #pragma unroll
                for (int dt = 0; dt < 8; dt++) {
                    uint32_t bv[2];
                    bv[0] = *reinterpret_cast<const uint32_t*>(&bufVT[dt * 8 + g][co]);
                    bv[1] = *reinterpret_cast<const uint32_t*>(&bufVT[dt * 8 + g][co + 8]);
                    mma_f16(O[dt], pa, bv);
                }
            }
        }
        __syncthreads();
    }

    float il0 = 1.f / l0, il1 = 1.f / l1;
    int r = row0 + g;
    __half* yb  = y + ((size_t)b * SEQT + r) * NE + h * HD;
    __half* yb8 = y + ((size_t)b * SEQT + r + 8) * NE + h * HD;
    #pragma unroll
    for (int dt = 0; dt < 8; dt++) {
        int c = dt * 8 + tg * 2;
        *reinterpret_cast<__half2*>(yb + c)  = __floats2half2_rn(O[dt][0] * il0, O[dt][1] * il0);
        *reinterpret_cast<__half2*>(yb8 + c) = __floats2half2_rn(O[dt][2] * il1, O[dt][3] * il1);
    }
}

// ------------------------- launch -------------------------
extern "C" void kernel_launch(void* const* d_in, const int* in_sizes, int n_in,
                              void* d_out, int out_size) {
    const float* x      = (const float*)d_in[0];
    const float* ln_w   = (const float*)d_in[1];
    const float* ln_b   = (const float*)d_in[2];
    const float* W_attn = (const float*)d_in[3];
    const float* b_attn = (const float*)d_in[4];
    const float* W_proj = (const float*)d_in[5];
    const float* b_proj = (const float*)d_in[6];
    float* out = (float*)d_out;

    __half *h, *qkv, *y, *wta, *wtp;
    cudaGetSymbolAddress((void**)&h,   g_h);
    cudaGetSymbolAddress((void**)&qkv, g_qkv);
    cudaGetSymbolAddress((void**)&y,   g_y);
    cudaGetSymbolAddress((void**)&wta, g_wta);
    cudaGetSymbolAddress((void**)&wtp, g_wtp);

    transpose_w<<<dim3(3 * NE / 32, CIN / 32), dim3(32, 8)>>>(W_attn, wta, CIN, 3 * NE);
    transpose_w<<<dim3(NE / 32, NE / 32),      dim3(32, 8)>>>(W_proj, wtp, NE, NE);
    ln_kernel<<<ROWS, 256>>>(x, ln_w, ln_b, h);
    gemm_f16<true><<<dim3(3 * NE / 128, ROWS / 128), 256>>>(h, wta, b_attn, qkv, ROWS, 3 * NE, CIN);
    attn_kernel<<<dim3(SEQT / 128, NH, BATCH), 256>>>(qkv, y);
    gemm_f16<false><<<dim3(NE / 128, ROWS / 128), 256>>>(y, wtp, b_proj, out, ROWS, NE, NE);
}

// round 14
// speedup vs baseline: 2.5180x; 1.1439x over previous
#include <cuda_runtime.h>
#include <cuda_fp16.h>
#include <cstdint>
#include <cstddef>

#define BATCH 4
#define SEQT  2048
#define CIN   1152
#define NE    1024
#define NH    16
#define HD    64
#define ROWS  (BATCH*SEQT)   // 8192

// ---- scratch (no allocations allowed) ----
__device__ __half g_h[(size_t)ROWS * CIN];
__device__ __half g_qkv[(size_t)ROWS * 3 * NE];
__device__ __half g_y[(size_t)ROWS * NE];
__device__ __half g_wta[(size_t)3 * NE * CIN];
__device__ __half g_wtp[(size_t)NE * NE];

__device__ __forceinline__ void mma_f16(float c[4], const uint32_t a[4], const uint32_t b[2]) {
    asm volatile(
        "mma.sync.aligned.m16n8k16.row.col.f32.f16.f16.f32 "
        "{%0,%1,%2,%3}, {%4,%5,%6,%7}, {%8,%9}, {%0,%1,%2,%3};\n"
        : "+f"(c[0]), "+f"(c[1]), "+f"(c[2]), "+f"(c[3])
        : "r"(a[0]), "r"(a[1]), "r"(a[2]), "r"(a[3]), "r"(b[0]), "r"(b[1]));
}

__device__ __forceinline__ uint32_t smem_u32(const void* p) {
    return (uint32_t)__cvta_generic_to_shared(p);
}
#define CP_ASYNC16(dst, src) \
    asm volatile("cp.async.cg.shared.global [%0], [%1], 16;\n" :: "r"(dst), "l"(src))
#define CP_COMMIT() asm volatile("cp.async.commit_group;\n")
#define CP_WAIT1()  asm volatile("cp.async.wait_group 1;\n")
#define CP_WAIT0()  asm volatile("cp.async.wait_group 0;\n")
#define LDSM_X4(r0, r1, r2, r3, addr) \
    asm volatile("ldmatrix.sync.aligned.m8n8.x4.shared.b16 {%0,%1,%2,%3}, [%4];" \
                 : "=r"(r0), "=r"(r1), "=r"(r2), "=r"(r3) : "r"(addr))
#define LDSM_X4_T(r0, r1, r2, r3, addr) \
    asm volatile("ldmatrix.sync.aligned.m8n8.x4.trans.shared.b16 {%0,%1,%2,%3}, [%4];" \
                 : "=r"(r0), "=r"(r1), "=r"(r2), "=r"(r3) : "r"(addr))

// ---------------- weight transpose + half convert ----------------
__global__ void transpose_w(const float* __restrict__ W, __half* __restrict__ wT, int K, int N) {
    __shared__ float t[32][33];
    int n0 = blockIdx.x * 32, k0 = blockIdx.y * 32;
    #pragma unroll
    for (int i = threadIdx.y; i < 32; i += 8)
        t[i][threadIdx.x] = W[(size_t)(k0 + i) * N + n0 + threadIdx.x];
    __syncthreads();
    #pragma unroll
    for (int i = threadIdx.y; i < 32; i += 8)
        wT[(size_t)(n0 + i) * K + k0 + threadIdx.x] = __float2half_rn(t[threadIdx.x][i]);
}

// ------------------------- LayerNorm -------------------------
__global__ void ln_kernel(const float* __restrict__ x, const float* __restrict__ w,
                          const float* __restrict__ bb, __half* __restrict__ h) {
    int row = blockIdx.x;
    const float2* xr = (const float2*)(x + (size_t)row * CIN);
    float s1 = 0.f, s2 = 0.f;
    for (int i = threadIdx.x; i < CIN / 2; i += 256) {
        float2 v = xr[i];
        s1 += v.x + v.y; s2 += v.x * v.x + v.y * v.y;
    }
    #pragma unroll
    for (int o = 16; o; o >>= 1) {
        s1 += __shfl_xor_sync(0xffffffffu, s1, o);
        s2 += __shfl_xor_sync(0xffffffffu, s2, o);
    }
    __shared__ float sh1[8], sh2[8];
    int wid = threadIdx.x >> 5, lane = threadIdx.x & 31;
    if (lane == 0) { sh1[wid] = s1; sh2[wid] = s2; }
    __syncthreads();
    float S1 = 0.f, S2 = 0.f;
    #pragma unroll
    for (int i = 0; i < 8; i++) { S1 += sh1[i]; S2 += sh2[i]; }
    float mean = S1 * (1.f / CIN);
    float var  = S2 * (1.f / CIN) - mean * mean;
    float inv  = rsqrtf(var + 1e-5f);
    const float2* w2 = (const float2*)w;
    const float2* b2 = (const float2*)bb;
    __half2* hr = (__half2*)(h + (size_t)row * CIN);
    for (int i = threadIdx.x; i < CIN / 2; i += 256) {
        float2 v = xr[i], ww = w2[i], bz = b2[i];
        hr[i] = __floats2half2_rn((v.x - mean) * inv * ww.x + bz.x,
                                  (v.y - mean) * inv * ww.y + bz.y);
    }
}

// ------------------------- fp16 GEMM: C = A@Bt^T + bias -------------------------
// 3-stage cp.async, 1 sync/iter, ldmatrix fragments. (R10-validated)
template<bool HALF_OUT>
__global__ __launch_bounds__(256) void gemm_f16(
        const __half* __restrict__ A, const __half* __restrict__ Bt,
        const float* __restrict__ bias, void* __restrict__ Cv,
        int M, int N, int K) {
    __shared__ __half As[3][128][40];
    __shared__ __half Bs[3][128][40];
    int tid = threadIdx.x;
    int lane = tid & 31, wid = tid >> 5;
    int wm = (wid & 3) * 32, wn = (wid >> 2) * 64;
    int bm = blockIdx.y * 128, bn = blockIdx.x * 128;
    int g = lane >> 2, tg = lane & 3;

    float acc[2][8][4];
    #pragma unroll
    for (int mt = 0; mt < 2; mt++)
        #pragma unroll
        for (int nt = 0; nt < 8; nt++)
            #pragma unroll
            for (int i = 0; i < 4; i++) acc[mt][nt][i] = 0.f;

    const __half* Abase = A + (size_t)bm * K;
    const __half* Bbase = Bt + (size_t)bn * K;
    int ktiles = K >> 5;

    int a_row = (lane & 7) + ((lane >> 3) & 1) * 8;
    int a_col = (lane >> 4) * 8;
    int b_row = (lane & 7) + (lane >> 4) * 8;
    int b_col = ((lane >> 3) & 1) * 8;

    int lr = tid >> 2, lc = (tid & 3) * 8;
    int lr2 = (tid + 256) >> 2, lc2 = ((tid + 256) & 3) * 8;

    #pragma unroll
    for (int s = 0; s < 2; s++) {
        int k0 = s << 5;
        CP_ASYNC16(smem_u32(&As[s][lr][lc]),  Abase + (size_t)lr * K + k0 + lc);
        CP_ASYNC16(smem_u32(&Bs[s][lr][lc]),  Bbase + (size_t)lr * K + k0 + lc);
        CP_ASYNC16(smem_u32(&As[s][lr2][lc2]), Abase + (size_t)lr2 * K + k0 + lc2);
        CP_ASYNC16(smem_u32(&Bs[s][lr2][lc2]), Bbase + (size_t)lr2 * K + k0 + lc2);
        CP_COMMIT();
    }

    for (int it = 0; it < ktiles; it++) {
        CP_WAIT1();
        __syncthreads();
        int cur = it % 3;

        #pragma unroll
        for (int ks = 0; ks < 2; ks++) {
            uint32_t a[2][4], b[8][2];
            #pragma unroll
            for (int mt = 0; mt < 2; mt++) {
                uint32_t addr = smem_u32(&As[cur][wm + mt * 16 + a_row][ks * 16 + a_col]);
                LDSM_X4(a[mt][0], a[mt][1], a[mt][2], a[mt][3], addr);
            }
            #pragma unroll
            for (int ntp = 0; ntp < 8; ntp += 2) {
                uint32_t addr = smem_u32(&Bs[cur][wn + ntp * 8 + b_row][ks * 16 + b_col]);
                LDSM_X4(b[ntp][0], b[ntp][1], b[ntp + 1][0], b[ntp + 1][1], addr);
            }
            #pragma unroll
            for (int mt = 0; mt < 2; mt++)
                #pragma unroll
                for (int nt = 0; nt < 8; nt++)
                    mma_f16(acc[mt][nt], a[mt], b[nt]);
        }

        int nt_ = it + 2;
        if (nt_ < ktiles) {
            int s = nt_ % 3, k0 = nt_ << 5;
            CP_ASYNC16(smem_u32(&As[s][lr][lc]),  Abase + (size_t)lr * K + k0 + lc);
            CP_ASYNC16(smem_u32(&Bs[s][lr][lc]),  Bbase + (size_t)lr * K + k0 + lc);
            CP_ASYNC16(smem_u32(&As[s][lr2][lc2]), Abase + (size_t)lr2 * K + k0 + lc2);
            CP_ASYNC16(smem_u32(&Bs[s][lr2][lc2]), Bbase + (size_t)lr2 * K + k0 + lc2);
        }
        CP_COMMIT();
    }

    #pragma unroll
    for (int mt = 0; mt < 2; mt++) {
        int r0 = bm + wm + mt * 16 + g;
        #pragma unroll
        for (int nt = 0; nt < 8; nt++) {
            int c0 = bn + wn + nt * 8 + tg * 2;
            float bz0 = bias[c0], bz1 = bias[c0 + 1];
            if (HALF_OUT) {
                __half* C = (__half*)Cv;
                *reinterpret_cast<__half2*>(C + (size_t)r0 * N + c0) =
                    __floats2half2_rn(acc[mt][nt][0] + bz0, acc[mt][nt][1] + bz1);
                *reinterpret_cast<__half2*>(C + (size_t)(r0 + 8) * N + c0) =
                    __floats2half2_rn(acc[mt][nt][2] + bz0, acc[mt][nt][3] + bz1);
            } else {
                float* C = (float*)Cv;
                C[(size_t)r0 * N + c0]           = acc[mt][nt][0] + bz0;
                C[(size_t)r0 * N + c0 + 1]       = acc[mt][nt][1] + bz1;
                C[(size_t)(r0 + 8) * N + c0]     = acc[mt][nt][2] + bz0;
                C[(size_t)(r0 + 8) * N + c0 + 1] = acc[mt][nt][3] + bz1;
            }
        }
    }
}

// ------------------------- Flash attention (causal, fp16 mma) -------------------------
// 128 q-rows/block, 8 warps. Double-buffered 128-token K/V tiles (both cp.async,
// token-major); K fragments via ldmatrix, V^T fragments via ldmatrix.trans.
__global__ __launch_bounds__(256, 2) void attn_kernel(const __half* __restrict__ qkv,
                                                      __half* __restrict__ y) {
    __shared__ __half bufK[2][128][72];
    __shared__ __half bufV[2][128][72];
    int qt = gridDim.x - 1 - blockIdx.x;     // heavy blocks launch first
    int h = blockIdx.y, b = blockIdx.z;
    int tid = threadIdx.x, lane = tid & 31, w = tid >> 5;
    int g = lane >> 2, tg = lane & 3;
    int q0 = qt * 128;
    int row0 = q0 + w * 16;
    const size_t rstr = (size_t)3 * NE;
    const __half* kbase = qkv + ((size_t)b * SEQT) * rstr + NE + h * HD;
    const __half* vbase = qkv + ((size_t)b * SEQT) * rstr + 2 * NE + h * HD;

    // ldmatrix lane mappings
    int krow = (lane & 7) + (lane >> 4) * 8;        // K non-trans (as gemm B)
    int kcol = ((lane >> 3) & 1) * 8;
    int vrow = (lane & 7) + ((lane >> 3) & 1) * 8;  // V trans
    int vcol = (lane >> 4) * 8;
    int lr = tid >> 3, lc = (tid & 7) * 8;          // cp.async coords (tasks 0..1023 over 4 iters)

    const __half2 sc2 = __float2half2_rn(0.125f);
    const __half* qbase = qkv + ((size_t)b * SEQT + row0) * rstr + h * HD;
    uint32_t qf[4][4];
    #pragma unroll
    for (int ks = 0; ks < 4; ks++) {
        int c = ks * 16 + tg * 2;
        __half2 v0 = __hmul2(*reinterpret_cast<const __half2*>(qbase + (size_t)g * rstr + c), sc2);
        __half2 v1 = __hmul2(*reinterpret_cast<const __half2*>(qbase + (size_t)(g + 8) * rstr + c), sc2);
        __half2 v2 = __hmul2(*reinterpret_cast<const __half2*>(qbase + (size_t)g * rstr + c + 8), sc2);
        __half2 v3 = __hmul2(*reinterpret_cast<const __half2*>(qbase + (size_t)(g + 8) * rstr + c + 8), sc2);
        qf[ks][0] = *reinterpret_cast<uint32_t*>(&v0);
        qf[ks][1] = *reinterpret_cast<uint32_t*>(&v1);
        qf[ks][2] = *reinterpret_cast<uint32_t*>(&v2);
        qf[ks][3] = *reinterpret_cast<uint32_t*>(&v3);
    }

    float O[8][4];
    #pragma unroll
    for (int dt = 0; dt < 8; dt++)
        #pragma unroll
        for (int i = 0; i < 4; i++) O[dt][i] = 0.f;
    float m0 = -1e30f, m1 = -1e30f, l0 = 0.f, l1 = 0.f;

    int ntile = qt + 1;

    // prologue: tile 0 -> buf 0 (one commit-group per tile)
    {
        int kb0 = 0;
        #pragma unroll
        for (int i = 0; i < 4; i++) {
            int r = lr + i * 32;
            CP_ASYNC16(smem_u32(&bufK[0][r][lc]), kbase + (size_t)(kb0 + r) * rstr + lc);
            CP_ASYNC16(smem_u32(&bufV[0][r][lc]), vbase + (size_t)(kb0 + r) * rstr + lc);
        }
        CP_COMMIT();
    }

    for (int kt = 0; kt < ntile; kt++) {
        int cur = kt & 1;
        if (kt + 1 < ntile) {
            int kb0 = (kt + 1) * 128;
            #pragma unroll
            for (int i = 0; i < 4; i++) {
                int r = lr + i * 32;
                CP_ASYNC16(smem_u32(&bufK[cur ^ 1][r][lc]), kbase + (size_t)(kb0 + r) * rstr + lc);
                CP_ASYNC16(smem_u32(&bufV[cur ^ 1][r][lc]), vbase + (size_t)(kb0 + r) * rstr + lc);
            }
            CP_COMMIT();
            CP_WAIT1();
        } else {
            CP_WAIT0();
        }
        __syncthreads();

        int kb0 = kt * 128;
        #pragma unroll
        for (int hf = 0; hf < 2; hf++) {
            int kb = kb0 + hf * 64;
            if (kb > row0 + 15) break;       // warp-uniform causal skip
            int ro = hf * 64;

            float S[8][4];
            #pragma unroll
            for (int nt = 0; nt < 8; nt++)
                #pragma unroll
                for (int i = 0; i < 4; i++) S[nt][i] = 0.f;
            #pragma unroll
            for (int ks = 0; ks < 4; ks++) {
                #pragma unroll
                for (int ntp = 0; ntp < 8; ntp += 2) {
                    uint32_t bk[2][2];
                    uint32_t addr = smem_u32(&bufK[cur][ro + ntp * 8 + krow][ks * 16 + kcol]);
                    LDSM_X4(bk[0][0], bk[0][1], bk[1][0], bk[1][1], addr);
                    mma_f16(S[ntp],     qf[ks], bk[0]);
                    mma_f16(S[ntp + 1], qf[ks], bk[1]);
                }
            }

            if (kb + 63 > row0) {
                int r = row0 + g;
                #pragma unroll
                for (int nt = 0; nt < 8; nt++) {
                    int c = kb + nt * 8 + tg * 2;
                    if (c     > r)     S[nt][0] = -1e30f;
                    if (c + 1 > r)     S[nt][1] = -1e30f;
                    if (c     > r + 8) S[nt][2] = -1e30f;
                    if (c + 1 > r + 8) S[nt][3] = -1e30f;
                }
            }

            float mx0 = -1e30f, mx1 = -1e30f;
            #pragma unroll
            for (int nt = 0; nt < 8; nt++) {
                mx0 = fmaxf(mx0, fmaxf(S[nt][0], S[nt][1]));
                mx1 = fmaxf(mx1, fmaxf(S[nt][2], S[nt][3]));
            }
            #pragma unroll
            for (int o = 1; o <= 2; o <<= 1) {
                mx0 = fmaxf(mx0, __shfl_xor_sync(0xffffffffu, mx0, o));
                mx1 = fmaxf(mx1, __shfl_xor_sync(0xffffffffu, mx1, o));
            }
            float nm0 = fmaxf(m0, mx0), nm1 = fmaxf(m1, mx1);
            float al0 = __expf(m0 - nm0), al1 = __expf(m1 - nm1);
            float rs0 = 0.f, rs1 = 0.f;
            #pragma unroll
            for (int nt = 0; nt < 8; nt++) {
                S[nt][0] = __expf(S[nt][0] - nm0); rs0 += S[nt][0];
                S[nt][1] = __expf(S[nt][1] - nm0); rs0 += S[nt][1];
                S[nt][2] = __expf(S[nt][2] - nm1); rs1 += S[nt][2];
                S[nt][3] = __expf(S[nt][3] - nm1); rs1 += S[nt][3];
            }
            #pragma unroll
            for (int o = 1; o <= 2; o <<= 1) {
                rs0 += __shfl_xor_sync(0xffffffffu, rs0, o);
                rs1 += __shfl_xor_sync(0xffffffffu, rs1, o);
            }
            l0 = l0 * al0 + rs0; l1 = l1 * al1 + rs1;
            m0 = nm0; m1 = nm1;
            #pragma unroll
            for (int dt = 0; dt < 8; dt++) {
                O[dt][0] *= al0; O[dt][1] *= al0; O[dt][2] *= al1; O[dt][3] *= al1;
            }

            #pragma unroll
            for (int ks = 0; ks < 4; ks++) {
                __half2 p0 = __floats2half2_rn(S[2 * ks][0],     S[2 * ks][1]);
                __half2 p1 = __floats2half2_rn(S[2 * ks][2],     S[2 * ks][3]);
                __half2 p2 = __floats2half2_rn(S[2 * ks + 1][0], S[2 * ks + 1][1]);
                __half2 p3 = __floats2half2_rn(S[2 * ks + 1][2], S[2 * ks + 1][3]);
                uint32_t pa[4];
                pa[0] = *reinterpret_cast<uint32_t*>(&p0);
                pa[1] = *reinterpret_cast<uint32_t*>(&p1);
                pa[2] = *reinterpret_cast<uint32_t*>(&p2);
                pa[3] = *reinterpret_cast<uint32_t*>(&p3);
                #pragma unroll
                for (int dtp = 0; dtp < 8; dtp += 2) {
                    uint32_t bv[2][2];
                    uint32_t addr = smem_u32(&bufV[cur][ro + ks * 16 + vrow][dtp * 8 + vcol]);
                    LDSM_X4_T(bv[0][0], bv[0][1], bv[1][0], bv[1][1], addr);
                    mma_f16(O[dtp],     pa, bv[0]);
                    mma_f16(O[dtp + 1], pa, bv[1]);
                }
            }
        }
        __syncthreads();
    }

    float il0 = 1.f / l0, il1 = 1.f / l1;
    int r = row0 + g;
    __half* yb  = y + ((size_t)b * SEQT + r) * NE + h * HD;
    __half* yb8 = y + ((size_t)b * SEQT + r + 8) * NE + h * HD;
    #pragma unroll
    for (int dt = 0; dt < 8; dt++) {
        int c = dt * 8 + tg * 2;
        *reinterpret_cast<__half2*>(yb + c)  = __floats2half2_rn(O[dt][0] * il0, O[dt][1] * il0);
        *reinterpret_cast<__half2*>(yb8 + c) = __floats2half2_rn(O[dt][2] * il1, O[dt][3] * il1);
    }
}

// ------------------------- launch -------------------------
extern "C" void kernel_launch(void* const* d_in, const int* in_sizes, int n_in,
                              void* d_out, int out_size) {
    const float* x      = (const float*)d_in[0];
    const float* ln_w   = (const float*)d_in[1];
    const float* ln_b   = (const float*)d_in[2];
    const float* W_attn = (const float*)d_in[3];
    const float* b_attn = (const float*)d_in[4];
    const float* W_proj = (const float*)d_in[5];
    const float* b_proj = (const float*)d_in[6];
    float* out = (float*)d_out;

    __half *h, *qkv, *y, *wta, *wtp;
    cudaGetSymbolAddress((void**)&h,   g_h);
    cudaGetSymbolAddress((void**)&qkv, g_qkv);
    cudaGetSymbolAddress((void**)&y,   g_y);
    cudaGetSymbolAddress((void**)&wta, g_wta);
    cudaGetSymbolAddress((void**)&wtp, g_wtp);

    transpose_w<<<dim3(3 * NE / 32, CIN / 32), dim3(32, 8)>>>(W_attn, wta, CIN, 3 * NE);
    transpose_w<<<dim3(NE / 32, NE / 32),      dim3(32, 8)>>>(W_proj, wtp, NE, NE);
    ln_kernel<<<ROWS, 256>>>(x, ln_w, ln_b, h);
    gemm_f16<true><<<dim3(3 * NE / 128, ROWS / 128), 256>>>(h, wta, b_attn, qkv, ROWS, 3 * NE, CIN);
    attn_kernel<<<dim3(SEQT / 128, NH, BATCH), 256>>>(qkv, y);
    gemm_f16<false><<<dim3(NE / 128, ROWS / 128), 256>>>(y, wtp, b_proj, out, ROWS, NE, NE);
}